// round 8
// baseline (speedup 1.0000x reference)
#include <cuda_runtime.h>
#include <math.h>

#define NSEG   4096
#define EMBD   128
#define CAND   32
#define NVOT   1048576
#define RS     129            // smem row stride (129 mod 32 == 1 -> conflict-free)

__device__ float g_agg[NSEG * EMBD];   // segment accumulator (2 MB)
__device__ int   g_idx_is32;           // 1 if index buffer is int32, 0 if int64

extern __shared__ float smem[];

__global__ void zero_agg_kernel() {
    int i = blockIdx.x * blockDim.x + threadIdx.x;   // grid sized exactly
    g_agg[i] = 0.0f;
    if (i == 0) g_idx_is32 = 0;
}

// Probe: OR the odd 32-bit words of the first NVOT ints of the index buffer.
// int64 storage (values < 4096): all high words zero  -> flag stays 0.
// int32 storage: odd positions hold sorted values up to 4095 -> flag becomes 1.
// Reading NVOT ints is in-bounds for BOTH layouts.
__global__ void detect_index_kernel(const int* __restrict__ raw) {
    int i = blockIdx.x * blockDim.x + threadIdx.x;   // i in [0, NVOT/2)
    int v = raw[2 * i + 1];
    unsigned any = __ballot_sync(0xffffffffu, v != 0);
    if ((threadIdx.x & 31) == 0 && any) atomicOr(&g_idx_is32, 1);
}

// One 32-wide output chunk of a dense layer, K from smem row, W row-major [K, ldw].
template<int K, bool RELU>
__device__ __forceinline__ void layer_chunk(const float* __restrict__ hrow,
                                            const float* __restrict__ W,
                                            const float* __restrict__ bvec,
                                            float* __restrict__ outp,
                                            int j0, int ldw) {
    float acc[32];
    #pragma unroll
    for (int j = 0; j < 32; j++) acc[j] = bvec[j0 + j];
    #pragma unroll 4
    for (int k = 0; k < K; k++) {
        float hk = hrow[k];
        const float4* wp = (const float4*)(W + (size_t)k * ldw + j0);
        #pragma unroll
        for (int q = 0; q < 8; q++) {
            float4 w = wp[q];
            acc[4*q+0] = fmaf(hk, w.x, acc[4*q+0]);
            acc[4*q+1] = fmaf(hk, w.y, acc[4*q+1]);
            acc[4*q+2] = fmaf(hk, w.z, acc[4*q+2]);
            acc[4*q+3] = fmaf(hk, w.w, acc[4*q+3]);
        }
    }
    #pragma unroll
    for (int j = 0; j < 32; j++) outp[j] = RELU ? fmaxf(acc[j], 0.0f) : acc[j];
}

// 128 voters per block, 256 threads: thread (v, half) computes 64 of the 128 outputs.
__global__ __launch_bounds__(256, 1)
void local_kernel(const float* __restrict__ x, const int* __restrict__ idx_raw,
                  const float* __restrict__ W1, const float* __restrict__ b1,
                  const float* __restrict__ W2, const float* __restrict__ b2,
                  const float* __restrict__ W3, const float* __restrict__ b3) {
    float* A = smem;                 // 128*RS
    float* B = smem + 128 * RS;      // 128*RS
    __shared__ int segs[128];

    int tid  = threadIdx.x;
    int v    = tid & 127;
    int half = tid >> 7;
    int jb   = half * 64;
    int gv   = blockIdx.x * 128 + v;

    if (tid < 128) {
        int gi = blockIdx.x * 128 + tid;
        segs[tid] = g_idx_is32 ? idx_raw[gi] : idx_raw[2 * gi];  // int32 vs int64 (LE low word)
    }

    // x row -> registers
    float xr[32];
    const float4* xp = (const float4*)(x + (size_t)gv * CAND);
    #pragma unroll
    for (int i = 0; i < 8; i++) {
        float4 t = xp[i];
        xr[4*i] = t.x; xr[4*i+1] = t.y; xr[4*i+2] = t.z; xr[4*i+3] = t.w;
    }

    // ---- layer 1: x(regs) @ W1 -> A, relu (K=32, fully unrolled so xr stays in regs)
    #pragma unroll
    for (int c = 0; c < 2; c++) {
        int j0 = jb + 32 * c;
        float acc[32];
        #pragma unroll
        for (int j = 0; j < 32; j++) acc[j] = b1[j0 + j];
        #pragma unroll
        for (int k = 0; k < 32; k++) {
            float hk = xr[k];
            const float4* wp = (const float4*)(W1 + (size_t)k * EMBD + j0);
            #pragma unroll
            for (int q = 0; q < 8; q++) {
                float4 w = wp[q];
                acc[4*q+0] = fmaf(hk, w.x, acc[4*q+0]);
                acc[4*q+1] = fmaf(hk, w.y, acc[4*q+1]);
                acc[4*q+2] = fmaf(hk, w.z, acc[4*q+2]);
                acc[4*q+3] = fmaf(hk, w.w, acc[4*q+3]);
            }
        }
        #pragma unroll
        for (int j = 0; j < 32; j++) A[v * RS + j0 + j] = fmaxf(acc[j], 0.0f);
    }
    __syncthreads();

    // ---- layer 2: A -> B, relu
    #pragma unroll
    for (int c = 0; c < 2; c++) {
        int j0 = jb + 32 * c;
        float tmp[32];
        layer_chunk<EMBD, true>(&A[v * RS], W2, b2, tmp, j0, EMBD);
        #pragma unroll
        for (int j = 0; j < 32; j++) B[v * RS + j0 + j] = tmp[j];
    }
    __syncthreads();

    // ---- layer 3: B -> A, +bias, no relu
    #pragma unroll
    for (int c = 0; c < 2; c++) {
        int j0 = jb + 32 * c;
        float tmp[32];
        layer_chunk<EMBD, false>(&B[v * RS], W3, b3, tmp, j0, EMBD);
        #pragma unroll
        for (int j = 0; j < 32; j++) A[v * RS + j0 + j] = tmp[j];
    }
    __syncthreads();

    // ---- sorted segment reduction: thread = (column j, voter-half)
    {
        int j = tid & 127;
        int vstart = half * 64, vend = vstart + 64;
        int vv = vstart;
        while (vv < vend) {
            int s = segs[vv];
            float sum = 0.0f;
            do { sum += A[vv * RS + j]; vv++; } while (vv < vend && segs[vv] == s);
            atomicAdd(&g_agg[(size_t)s * EMBD + j], sum);
        }
    }
}

// 128 segments per block, 1 thread per segment.
__global__ __launch_bounds__(128, 1)
void global_kernel(const float* __restrict__ W1, const float* __restrict__ b1,
                   const float* __restrict__ W2, const float* __restrict__ b2,
                   const float* __restrict__ W3, const float* __restrict__ b3,
                   float* __restrict__ out) {
    float* A = smem;
    float* B = smem + 128 * RS;
    int tid = threadIdx.x;
    int s0  = blockIdx.x * 128;

    // stage agg rows into A
    for (int i = tid; i < 128 * EMBD; i += 128) {
        int r = i >> 7, k = i & 127;
        A[r * RS + k] = g_agg[(size_t)(s0 + r) * EMBD + k];
    }
    __syncthreads();

    // layer 1: A -> B relu
    #pragma unroll
    for (int c = 0; c < 4; c++) {
        float tmp[32];
        layer_chunk<EMBD, true>(&A[tid * RS], W1, b1, tmp, 32 * c, EMBD);
        #pragma unroll
        for (int j = 0; j < 32; j++) B[tid * RS + 32 * c + j] = tmp[j];
    }
    __syncthreads();

    // layer 2: B -> A relu
    #pragma unroll
    for (int c = 0; c < 4; c++) {
        float tmp[32];
        layer_chunk<EMBD, true>(&B[tid * RS], W2, b2, tmp, 32 * c, EMBD);
        #pragma unroll
        for (int j = 0; j < 32; j++) A[tid * RS + 32 * c + j] = tmp[j];
    }
    __syncthreads();

    // layer 3: A -> scores[32] (W3 is [128,32]), then log_softmax
    float sc[32];
    layer_chunk<EMBD, false>(&A[tid * RS], W3, b3, sc, 0, CAND);

    float m = sc[0];
    #pragma unroll
    for (int j = 1; j < 32; j++) m = fmaxf(m, sc[j]);
    float sum = 0.0f;
    #pragma unroll
    for (int j = 0; j < 32; j++) sum += expf(sc[j] - m);
    float lse = m + logf(sum);

    float* op = out + (size_t)(s0 + tid) * CAND;
    #pragma unroll
    for (int j = 0; j < 32; j++) op[j] = sc[j] - lse;
}

extern "C" void kernel_launch(void* const* d_in, const int* in_sizes, int n_in,
                              void* d_out, int out_size) {
    const float* x       = (const float*)d_in[0];
    const int*   idx_raw = (const int*)d_in[1];   // int32 OR int64 — detected at runtime
    const float* lW1 = (const float*)d_in[2];  const float* lb1 = (const float*)d_in[3];
    const float* lW2 = (const float*)d_in[4];  const float* lb2 = (const float*)d_in[5];
    const float* lW3 = (const float*)d_in[6];  const float* lb3 = (const float*)d_in[7];
    const float* gW1 = (const float*)d_in[8];  const float* gb1 = (const float*)d_in[9];
    const float* gW2 = (const float*)d_in[10]; const float* gb2 = (const float*)d_in[11];
    const float* gW3 = (const float*)d_in[12]; const float* gb3 = (const float*)d_in[13];
    float* out = (float*)d_out;

    const int SMEM_BYTES = 2 * 128 * RS * sizeof(float);   // 132096
    static bool attr_done = false;
    if (!attr_done) {
        cudaFuncSetAttribute(local_kernel,  cudaFuncAttributeMaxDynamicSharedMemorySize, SMEM_BYTES);
        cudaFuncSetAttribute(global_kernel, cudaFuncAttributeMaxDynamicSharedMemorySize, SMEM_BYTES);
        attr_done = true;
    }

    zero_agg_kernel<<<NSEG * EMBD / 512, 512>>>();
    detect_index_kernel<<<(NVOT / 2) / 512, 512>>>(idx_raw);
    local_kernel<<<NVOT / 128, 256, SMEM_BYTES>>>(x, idx_raw, lW1, lb1, lW2, lb2, lW3, lb3);
    global_kernel<<<NSEG / 128, 128, SMEM_BYTES>>>(gW1, gb1, gW2, gb2, gW3, gb3, out);
}

// round 14
// speedup vs baseline: 1.0348x; 1.0348x over previous
#include <cuda_runtime.h>
#include <math.h>

#define NSEG   4096
#define EMBD   128
#define CAND   32
#define NVOT   1048576
#define RS     129            // smem row stride (129 mod 32 == 1 -> conflict-free)
#define VPB    64             // voters per block (local kernel)
#define SPB    32             // segments per block (global kernel)

__device__ float g_agg[NSEG * EMBD];   // segment accumulator (2 MB)
__device__ int   g_idx_is32;           // 1 if index buffer is int32, 0 if int64

extern __shared__ float smem[];

__global__ void zero_agg_kernel() {
    int i = blockIdx.x * blockDim.x + threadIdx.x;   // grid sized exactly
    g_agg[i] = 0.0f;
    if (i == 0) g_idx_is32 = 0;
}

// Probe: OR the odd 32-bit words of the first NVOT ints of the index buffer.
// int64 storage (values < 4096): all high words zero  -> flag stays 0.
// int32 storage: odd positions hold sorted nonzero values -> flag becomes 1.
__global__ void detect_index_kernel(const int* __restrict__ raw) {
    int i = blockIdx.x * blockDim.x + threadIdx.x;   // i in [0, NVOT/2)
    int v = raw[2 * i + 1];
    unsigned any = __ballot_sync(0xffffffffu, v != 0);
    if ((threadIdx.x & 31) == 0 && any) atomicOr(&g_idx_is32, 1);
}

// ---------------- packed f32x2 helpers ----------------
__device__ __forceinline__ unsigned long long pk2(float v) {
    unsigned long long r;
    asm("mov.b64 %0, {%1, %1};" : "=l"(r) : "f"(v));
    return r;
}
__device__ __forceinline__ void fma2(unsigned long long& d,
                                     unsigned long long a, unsigned long long b) {
    asm("fma.rn.f32x2 %0, %1, %2, %0;" : "+l"(d) : "l"(a), "l"(b));
}
__device__ __forceinline__ float2 upk(unsigned long long v) {
    float2 f;
    asm("mov.b64 {%0, %1}, %2;" : "=f"(f.x), "=f"(f.y) : "l"(v));
    return f;
}

// One 32-wide output chunk of a dense layer via packed f32x2 FMA.
// hrow: K floats (smem). W row-major [K, ldw], 16B-aligned at (k*ldw + j0).
template<int K, bool RELU>
__device__ __forceinline__ void layer_chunk2(const float* __restrict__ hrow,
                                             const float* __restrict__ W,
                                             const float* __restrict__ bvec,
                                             float* __restrict__ outp,
                                             int j0, int ldw) {
    unsigned long long acc[16];
    const ulonglong2* bp = (const ulonglong2*)(bvec + j0);
    #pragma unroll
    for (int q = 0; q < 8; q++) { ulonglong2 t = bp[q]; acc[2*q] = t.x; acc[2*q+1] = t.y; }
    #pragma unroll 4
    for (int k = 0; k < K; k++) {
        unsigned long long h2 = pk2(hrow[k]);
        const ulonglong2* wp = (const ulonglong2*)(W + (size_t)k * ldw + j0);
        #pragma unroll
        for (int q = 0; q < 8; q++) {
            ulonglong2 w = wp[q];
            fma2(acc[2*q],     w.x, h2);
            fma2(acc[2*q + 1], w.y, h2);
        }
    }
    #pragma unroll
    for (int q = 0; q < 16; q++) {
        float2 f = upk(acc[q]);
        outp[2*q]     = RELU ? fmaxf(f.x, 0.0f) : f.x;
        outp[2*q + 1] = RELU ? fmaxf(f.y, 0.0f) : f.y;
    }
}

// 64 voters per block, 128 threads: thread (v, half) computes 64 of the 128 outputs.
// smem: A = 64*RS, B = 64*RS  (66 KB -> 3 blocks/SM, 12 warps/SM)
__global__ __launch_bounds__(128, 3)
void local_kernel(const float* __restrict__ x, const int* __restrict__ idx_raw,
                  const float* __restrict__ W1, const float* __restrict__ b1,
                  const float* __restrict__ W2, const float* __restrict__ b2,
                  const float* __restrict__ W3, const float* __restrict__ b3) {
    float* A = smem;                // 64*RS
    float* B = smem + VPB * RS;     // 64*RS
    __shared__ int segs[VPB];

    int tid  = threadIdx.x;
    int v    = tid & 63;
    int half = tid >> 6;
    int jb   = half * 64;

    if (tid < VPB) {
        int gi = blockIdx.x * VPB + tid;
        segs[tid] = g_idx_is32 ? idx_raw[gi] : idx_raw[2 * gi];  // int32 vs int64 (LE low word)
    }

    // stage x rows into B[:, 0:32] (coalesced float4 global reads)
    {
        const float4* xs = (const float4*)(x + (size_t)blockIdx.x * VPB * CAND);
        #pragma unroll
        for (int it = 0; it < 4; it++) {
            int i = tid + it * 128;            // i in [0, 512): float4 index within block
            float4 t = xs[i];
            int row = i >> 3, c4 = (i & 7) * 4;
            B[row * RS + c4 + 0] = t.x;
            B[row * RS + c4 + 1] = t.y;
            B[row * RS + c4 + 2] = t.z;
            B[row * RS + c4 + 3] = t.w;
        }
    }
    __syncthreads();

    // ---- layer 1: B(x) -> A, relu (K=32)
    #pragma unroll
    for (int c = 0; c < 2; c++) {
        int j0 = jb + 32 * c;
        layer_chunk2<CAND, true>(&B[v * RS], W1, b1, &A[v * RS + j0], j0, EMBD);
    }
    __syncthreads();

    // ---- layer 2: A -> B, relu
    #pragma unroll
    for (int c = 0; c < 2; c++) {
        int j0 = jb + 32 * c;
        layer_chunk2<EMBD, true>(&A[v * RS], W2, b2, &B[v * RS + j0], j0, EMBD);
    }
    __syncthreads();

    // ---- layer 3: B -> A, +bias, no relu
    #pragma unroll
    for (int c = 0; c < 2; c++) {
        int j0 = jb + 32 * c;
        layer_chunk2<EMBD, false>(&B[v * RS], W3, b3, &A[v * RS + j0], j0, EMBD);
    }
    __syncthreads();

    // ---- sorted segment reduction: thread j sums column j over voter runs
    {
        int j = tid;                // 0..127
        int vv = 0;
        while (vv < VPB) {
            int s = segs[vv];
            float sum = 0.0f;
            do { sum += A[vv * RS + j]; vv++; } while (vv < VPB && segs[vv] == s);
            atomicAdd(&g_agg[(size_t)s * EMBD + j], sum);
        }
    }
}

// 32 segments per block, 128 threads: thread (s, c) computes 32 of the 128 outputs.
__global__ __launch_bounds__(128, 4)
void global_kernel(const float* __restrict__ W1, const float* __restrict__ b1,
                   const float* __restrict__ W2, const float* __restrict__ b2,
                   const float* __restrict__ W3, const float* __restrict__ b3,
                   float* __restrict__ out) {
    float* A = smem;                // 32*RS
    float* B = smem + SPB * RS;     // 32*RS
    int tid = threadIdx.x;
    int s   = tid >> 2;             // segment within block
    int c   = tid & 3;              // 32-wide output chunk
    int s0  = blockIdx.x * SPB;

    // stage agg rows into A (coalesced)
    for (int i = tid; i < SPB * EMBD; i += 128) {
        int r = i >> 7, k = i & 127;
        A[r * RS + k] = g_agg[(size_t)(s0 + r) * EMBD + k];
    }
    __syncthreads();

    // layer 1: A -> B relu
    layer_chunk2<EMBD, true>(&A[s * RS], W1, b1, &B[s * RS + 32 * c], 32 * c, EMBD);
    __syncthreads();

    // layer 2: B -> A relu
    layer_chunk2<EMBD, true>(&B[s * RS], W2, b2, &A[s * RS + 32 * c], 32 * c, EMBD);
    __syncthreads();

    // layer 3 + log_softmax: one thread per segment (c == 0)
    if (c == 0) {
        float sc[32];
        layer_chunk2<EMBD, false>(&A[s * RS], W3, b3, sc, 0, CAND);

        float m = sc[0];
        #pragma unroll
        for (int j = 1; j < 32; j++) m = fmaxf(m, sc[j]);
        float sum = 0.0f;
        #pragma unroll
        for (int j = 0; j < 32; j++) sum += expf(sc[j] - m);
        float lse = m + logf(sum);

        float* op = out + (size_t)(s0 + s) * CAND;
        #pragma unroll
        for (int j = 0; j < 32; j++) op[j] = sc[j] - lse;
    }
}

extern "C" void kernel_launch(void* const* d_in, const int* in_sizes, int n_in,
                              void* d_out, int out_size) {
    const float* x       = (const float*)d_in[0];
    const int*   idx_raw = (const int*)d_in[1];   // int32 OR int64 — detected at runtime
    const float* lW1 = (const float*)d_in[2];  const float* lb1 = (const float*)d_in[3];
    const float* lW2 = (const float*)d_in[4];  const float* lb2 = (const float*)d_in[5];
    const float* lW3 = (const float*)d_in[6];  const float* lb3 = (const float*)d_in[7];
    const float* gW1 = (const float*)d_in[8];  const float* gb1 = (const float*)d_in[9];
    const float* gW2 = (const float*)d_in[10]; const float* gb2 = (const float*)d_in[11];
    const float* gW3 = (const float*)d_in[12]; const float* gb3 = (const float*)d_in[13];
    float* out = (float*)d_out;

    const int SMEM_LOCAL  = 2 * VPB * RS * sizeof(float);   // 66048
    const int SMEM_GLOBAL = 2 * SPB * RS * sizeof(float);   // 33024
    cudaFuncSetAttribute(local_kernel,  cudaFuncAttributeMaxDynamicSharedMemorySize, SMEM_LOCAL);
    cudaFuncSetAttribute(global_kernel, cudaFuncAttributeMaxDynamicSharedMemorySize, SMEM_GLOBAL);

    zero_agg_kernel<<<NSEG * EMBD / 512, 512>>>();
    detect_index_kernel<<<(NVOT / 2) / 512, 512>>>(idx_raw);
    local_kernel<<<NVOT / VPB, 128, SMEM_LOCAL>>>(x, idx_raw, lW1, lb1, lW2, lb2, lW3, lb3);
    global_kernel<<<NSEG / SPB, 128, SMEM_GLOBAL>>>(gW1, gb1, gW2, gb2, gW3, gb3, out);
}

// round 15
// speedup vs baseline: 1.8336x; 1.7720x over previous
#include <cuda_runtime.h>
#include <math.h>

#define NSEG   4096
#define EMBD   128
#define CAND   32
#define NVOT   1048576
#define RS     129            // smem row stride (129 mod 32 == 1 -> conflict-free)
#define VPB    64             // voters per block (local kernel)
#define SPB    32             // segments per block (global kernel)
#define WCHF   (32 * 128)     // floats per weight chunk (32 k-rows x 128 cols)

__device__ float g_agg[NSEG * EMBD];   // segment accumulator (2 MB)
__device__ int   g_idx_is32;           // 1 if index buffer is int32, 0 if int64

extern __shared__ float smem[];

__global__ void zero_agg_kernel() {
    int i = blockIdx.x * blockDim.x + threadIdx.x;   // grid sized exactly
    g_agg[i] = 0.0f;
    if (i == 0) g_idx_is32 = 0;
}

// Probe: int64 storage (values < 4096) has all-zero odd words; int32 doesn't.
__global__ void detect_index_kernel(const int* __restrict__ raw) {
    int i = blockIdx.x * blockDim.x + threadIdx.x;   // i in [0, NVOT/2)
    int v = raw[2 * i + 1];
    unsigned any = __ballot_sync(0xffffffffu, v != 0);
    if ((threadIdx.x & 31) == 0 && any) atomicOr(&g_idx_is32, 1);
}

// ---------------- packed f32x2 helpers ----------------
__device__ __forceinline__ unsigned long long pk2(float v) {
    unsigned long long r;
    asm("mov.b64 %0, {%1, %1};" : "=l"(r) : "f"(v));
    return r;
}
__device__ __forceinline__ void fma2(unsigned long long& d,
                                     unsigned long long a, unsigned long long b) {
    asm("fma.rn.f32x2 %0, %1, %2, %0;" : "+l"(d) : "l"(a), "l"(b));
}
__device__ __forceinline__ float2 upk(unsigned long long v) {
    float2 f;
    asm("mov.b64 {%0, %1}, %2;" : "=f"(f.x), "=f"(f.y) : "l"(v));
    return f;
}

// ---------------- cp.async helpers ----------------
__device__ __forceinline__ void cpa16(unsigned int saddr, const void* gaddr) {
    asm volatile("cp.async.ca.shared.global [%0], [%1], 16;" :: "r"(saddr), "l"(gaddr));
}
#define CP_COMMIT() asm volatile("cp.async.commit_group;" ::: "memory")
#define CP_WAIT1()  asm volatile("cp.async.wait_group 1;" ::: "memory")
#define CP_WAIT0()  asm volatile("cp.async.wait_group 0;" ::: "memory")

// Cooperative async copy of one 32x128 fp32 weight chunk (16 KB) into smem.
__device__ __forceinline__ void load_chunk_async(float* wb, const float* __restrict__ Wsrc, int tid) {
    unsigned int s = (unsigned int)__cvta_generic_to_shared(wb);
    const float4* src = (const float4*)Wsrc;
    #pragma unroll
    for (int i = 0; i < 8; i++) {
        int idx = tid + i * 128;               // 1024 float4 total
        cpa16(s + idx * 16, src + idx);
    }
    CP_COMMIT();
}

// Accumulate one 32-deep K-chunk into a persistent 64-wide f32x2 accumulator.
// hbase: 32 activations (smem, per-voter). wb: chunk w[kk*128 + j] (smem, broadcast).
__device__ __forceinline__ void compute_chunk(const float* __restrict__ hbase,
                                              const float* __restrict__ wb,
                                              int jb, unsigned long long acc[32]) {
    #pragma unroll 2
    for (int kk = 0; kk < 32; kk++) {
        unsigned long long h2 = pk2(hbase[kk]);
        const ulonglong2* wp = (const ulonglong2*)(wb + kk * 128 + jb);
        #pragma unroll
        for (int q = 0; q < 16; q++) {
            ulonglong2 w = wp[q];
            fma2(acc[2*q],     w.x, h2);
            fma2(acc[2*q + 1], w.y, h2);
        }
    }
}

__device__ __forceinline__ void init_acc(unsigned long long acc[32],
                                         const float* __restrict__ bvec, int jb) {
    const ulonglong2* bp = (const ulonglong2*)(bvec + jb);
    #pragma unroll
    for (int q = 0; q < 16; q++) { ulonglong2 t = bp[q]; acc[2*q] = t.x; acc[2*q+1] = t.y; }
}

__device__ __forceinline__ void store_acc(float* __restrict__ dst,
                                          const unsigned long long acc[32], bool relu) {
    #pragma unroll
    for (int q = 0; q < 32; q++) {
        float2 f = upk(acc[q]);
        dst[2*q]     = relu ? fmaxf(f.x, 0.0f) : f.x;
        dst[2*q + 1] = relu ? fmaxf(f.y, 0.0f) : f.y;
    }
}

// 64 voters/block, 128 threads. Thread (v, half) owns a persistent 64-wide output
// slice per layer. Weights stream global->smem via double-buffered cp.async; all
// inner-loop operands come from smem. smem = 33K(A) + 33K(B) + 32K(wbuf) = 98.8 KB
// -> 2 blocks/SM.
__global__ __launch_bounds__(128, 2)
void local_kernel(const float* __restrict__ x, const int* __restrict__ idx_raw,
                  const float* __restrict__ W1, const float* __restrict__ b1,
                  const float* __restrict__ W2, const float* __restrict__ b2,
                  const float* __restrict__ W3, const float* __restrict__ b3) {
    float* A  = smem;                      // VPB*RS
    float* B  = smem + VPB * RS;           // VPB*RS
    float* W0 = smem + 2 * VPB * RS;       // weight buf 0 (WCHF floats)
    float* Wb1 = W0 + WCHF;                // weight buf 1
    __shared__ int segs[VPB];

    int tid  = threadIdx.x;
    int v    = tid & 63;
    int half = tid >> 6;
    int jb   = half * 64;

    if (tid < VPB) {
        int gi = blockIdx.x * VPB + tid;
        segs[tid] = g_idx_is32 ? idx_raw[gi] : idx_raw[2 * gi];  // int32 vs int64 (LE low word)
    }

    // prologue: prefetch chunk 0 (= W1, exactly 32x128)
    load_chunk_async(W0, W1, tid);

    // stage x rows into A[:, 0:32] (coalesced float4 global reads)
    {
        const float4* xs = (const float4*)(x + (size_t)blockIdx.x * VPB * CAND);
        #pragma unroll
        for (int it = 0; it < 4; it++) {
            int i = tid + it * 128;            // 512 float4 within block
            float4 t = xs[i];
            int row = i >> 3, c4 = (i & 7) * 4;
            A[row * RS + c4 + 0] = t.x;
            A[row * RS + c4 + 1] = t.y;
            A[row * RS + c4 + 2] = t.z;
            A[row * RS + c4 + 3] = t.w;
        }
    }

    unsigned long long acc[32];

    // ---- phase 0: layer 1 (K=32), chunk0 in W0; prefetch chunk1 (W2 rows 0:32)
    load_chunk_async(Wb1, W2, tid);
    CP_WAIT1();
    __syncthreads();
    init_acc(acc, b1, jb);
    compute_chunk(&A[v * RS], W0, jb, acc);
    store_acc(&B[v * RS + jb], acc, true);
    __syncthreads();

    // ---- phases 1..4: layer 2 chunks 0..3 (h from B), persistent acc; store -> A
    init_acc(acc, b2, jb);
    #pragma unroll
    for (int p = 1; p <= 4; p++) {
        const float* nsrc = (p <= 3) ? (W2 + p * WCHF) : W3;   // chunk p+1 source
        load_chunk_async(((p + 1) & 1) ? Wb1 : W0, nsrc, tid);
        CP_WAIT1();
        __syncthreads();
        compute_chunk(&B[v * RS + (p - 1) * 32], (p & 1) ? Wb1 : W0, jb, acc);
        if (p == 4) store_acc(&A[v * RS + jb], acc, true);
        __syncthreads();
    }

    // ---- phases 5..8: layer 3 chunks 0..3 (h from A), store -> B (no relu)
    init_acc(acc, b3, jb);
    #pragma unroll
    for (int p = 5; p <= 8; p++) {
        if (p <= 7) {
            load_chunk_async(((p + 1) & 1) ? Wb1 : W0, W3 + (p - 4) * WCHF, tid);
            CP_WAIT1();
        } else {
            CP_WAIT0();
        }
        __syncthreads();
        compute_chunk(&A[v * RS + (p - 5) * 32], (p & 1) ? Wb1 : W0, jb, acc);
        if (p == 8) store_acc(&B[v * RS + jb], acc, false);
        __syncthreads();
    }

    // ---- sorted segment reduction: thread j sums column j over voter runs (reads B)
    {
        int j = tid;                // 0..127
        int vv = 0;
        while (vv < VPB) {
            int s = segs[vv];
            float sum = 0.0f;
            do { sum += B[vv * RS + j]; vv++; } while (vv < VPB && segs[vv] == s);
            atomicAdd(&g_agg[(size_t)s * EMBD + j], sum);
        }
    }
}

// ---------------- global MLP (unchanged from R14, 112us) ----------------
template<int K, bool RELU>
__device__ __forceinline__ void layer_chunk2(const float* __restrict__ hrow,
                                             const float* __restrict__ W,
                                             const float* __restrict__ bvec,
                                             float* __restrict__ outp,
                                             int j0, int ldw) {
    unsigned long long acc[16];
    const ulonglong2* bp = (const ulonglong2*)(bvec + j0);
    #pragma unroll
    for (int q = 0; q < 8; q++) { ulonglong2 t = bp[q]; acc[2*q] = t.x; acc[2*q+1] = t.y; }
    #pragma unroll 4
    for (int k = 0; k < K; k++) {
        unsigned long long h2 = pk2(hrow[k]);
        const ulonglong2* wp = (const ulonglong2*)(W + (size_t)k * ldw + j0);
        #pragma unroll
        for (int q = 0; q < 8; q++) {
            ulonglong2 w = wp[q];
            fma2(acc[2*q],     w.x, h2);
            fma2(acc[2*q + 1], w.y, h2);
        }
    }
    #pragma unroll
    for (int q = 0; q < 16; q++) {
        float2 f = upk(acc[q]);
        outp[2*q]     = RELU ? fmaxf(f.x, 0.0f) : f.x;
        outp[2*q + 1] = RELU ? fmaxf(f.y, 0.0f) : f.y;
    }
}

__global__ __launch_bounds__(128, 4)
void global_kernel(const float* __restrict__ W1, const float* __restrict__ b1,
                   const float* __restrict__ W2, const float* __restrict__ b2,
                   const float* __restrict__ W3, const float* __restrict__ b3,
                   float* __restrict__ out) {
    float* A = smem;                // 32*RS
    float* B = smem + SPB * RS;     // 32*RS
    int tid = threadIdx.x;
    int s   = tid >> 2;             // segment within block
    int c   = tid & 3;              // 32-wide output chunk
    int s0  = blockIdx.x * SPB;

    for (int i = tid; i < SPB * EMBD; i += 128) {
        int r = i >> 7, k = i & 127;
        A[r * RS + k] = g_agg[(size_t)(s0 + r) * EMBD + k];
    }
    __syncthreads();

    layer_chunk2<EMBD, true>(&A[s * RS], W1, b1, &B[s * RS + 32 * c], 32 * c, EMBD);
    __syncthreads();

    layer_chunk2<EMBD, true>(&B[s * RS], W2, b2, &A[s * RS + 32 * c], 32 * c, EMBD);
    __syncthreads();

    if (c == 0) {
        float sc[32];
        layer_chunk2<EMBD, false>(&A[s * RS], W3, b3, sc, 0, CAND);

        float m = sc[0];
        #pragma unroll
        for (int j = 1; j < 32; j++) m = fmaxf(m, sc[j]);
        float sum = 0.0f;
        #pragma unroll
        for (int j = 0; j < 32; j++) sum += expf(sc[j] - m);
        float lse = m + logf(sum);

        float* op = out + (size_t)(s0 + s) * CAND;
        #pragma unroll
        for (int j = 0; j < 32; j++) op[j] = sc[j] - lse;
    }
}

extern "C" void kernel_launch(void* const* d_in, const int* in_sizes, int n_in,
                              void* d_out, int out_size) {
    const float* x       = (const float*)d_in[0];
    const int*   idx_raw = (const int*)d_in[1];   // int32 OR int64 — detected at runtime
    const float* lW1 = (const float*)d_in[2];  const float* lb1 = (const float*)d_in[3];
    const float* lW2 = (const float*)d_in[4];  const float* lb2 = (const float*)d_in[5];
    const float* lW3 = (const float*)d_in[6];  const float* lb3 = (const float*)d_in[7];
    const float* gW1 = (const float*)d_in[8];  const float* gb1 = (const float*)d_in[9];
    const float* gW2 = (const float*)d_in[10]; const float* gb2 = (const float*)d_in[11];
    const float* gW3 = (const float*)d_in[12]; const float* gb3 = (const float*)d_in[13];
    float* out = (float*)d_out;

    const int SMEM_LOCAL  = (2 * VPB * RS + 2 * WCHF) * sizeof(float);  // 98816
    const int SMEM_GLOBAL = 2 * SPB * RS * sizeof(float);               // 33024
    cudaFuncSetAttribute(local_kernel,  cudaFuncAttributeMaxDynamicSharedMemorySize, SMEM_LOCAL);
    cudaFuncSetAttribute(global_kernel, cudaFuncAttributeMaxDynamicSharedMemorySize, SMEM_GLOBAL);

    zero_agg_kernel<<<NSEG * EMBD / 512, 512>>>();
    detect_index_kernel<<<(NVOT / 2) / 512, 512>>>(idx_raw);
    local_kernel<<<NVOT / VPB, 128, SMEM_LOCAL>>>(x, idx_raw, lW1, lb1, lW2, lb2, lW3, lb3);
    global_kernel<<<NSEG / SPB, 128, SMEM_GLOBAL>>>(gW1, gb1, gW2, gb2, gW3, gb3, out);
}

// round 17
// speedup vs baseline: 6.1093x; 3.3319x over previous
#include <cuda_runtime.h>
#include <cstdint>
#include <math.h>

#define NSEG   4096
#define EMBD   128
#define CAND   32
#define NVOT   1048576
#define NTILE  (NVOT / 128)
#define RS     129
#define SPB    32
#define ACTS   132           // act row stride (words); 132%32=4 -> conflict-free frag access

// smem word offsets (local_kernel)
#define OFF_BF1   0          // W1 frags  4096 words
#define OFF_BF2   4096       // W2 frags 16384 words
#define OFF_BF3   20480      // W3 frags 16384 words
#define OFF_ACT   36864      // 128 x 132 activation/HAT buffer = 16896 words
#define OFF_B1    53760
#define OFF_B2    53888
#define OFF_B3    54016
#define SMEM_LOCAL_WORDS 54144
#define SMEM_LOCAL (SMEM_LOCAL_WORDS * 4)   // 216576 B

__device__ float    g_agg[NSEG * EMBD];
__device__ int      g_idx_is32;
__device__ uint32_t g_bfrag[36864];   // pre-packed tf32 B fragments: W1|W2|W3

extern __shared__ uint32_t smu[];

// ---------------- helpers ----------------
__device__ __forceinline__ uint32_t f2tf(float v) {
    uint32_t r;
    asm("cvt.rna.tf32.f32 %0, %1;" : "=r"(r) : "f"(v));
    return r;
}

__device__ __forceinline__ void mma_tf32(float c[4],
                                         uint32_t a0, uint32_t a1, uint32_t a2, uint32_t a3,
                                         uint32_t b0, uint32_t b1) {
    asm("mma.sync.aligned.m16n8k8.row.col.f32.tf32.tf32.f32 "
        "{%0,%1,%2,%3}, {%4,%5,%6,%7}, {%8,%9}, {%0,%1,%2,%3};"
        : "+f"(c[0]), "+f"(c[1]), "+f"(c[2]), "+f"(c[3])
        : "r"(a0), "r"(a1), "r"(a2), "r"(a3), "r"(b0), "r"(b1));
}

// ---------------- setup kernels ----------------
__global__ void zero_agg_kernel() {
    int i = blockIdx.x * blockDim.x + threadIdx.x;
    g_agg[i] = 0.0f;
    if (i == 0) g_idx_is32 = 0;
}

// int64 storage (values < 4096) has all-zero odd words; int32 doesn't.
__global__ void detect_index_kernel(const int* __restrict__ raw) {
    int i = blockIdx.x * blockDim.x + threadIdx.x;   // [0, NVOT/2)
    int v = raw[2 * i + 1];
    unsigned any = __ballot_sync(0xffffffffu, v != 0);
    if ((threadIdx.x & 31) == 0 && any) atomicOr(&g_idx_is32, 1);
}

// Pack B fragments for mma.m16n8k8.tf32 (.row.col):
//   b0 = W[kc*8 + lane%4][nt*8 + lane/4], b1 = same with k+4, tf32-rounded.
// Layout: [kc][nt][lane][2]  -> per-mma load is one lane-linear LDS.64.
__global__ void wprep_kernel(const float* __restrict__ W1,
                             const float* __restrict__ W2,
                             const float* __restrict__ W3) {
    int id = blockIdx.x * blockDim.x + threadIdx.x;   // 0..18431 (pairs)
    const float* W;
    uint32_t* dst;
    int t;
    if (id < 2048)       { W = W1; dst = g_bfrag;          t = id; }
    else if (id < 10240) { W = W2; dst = g_bfrag + 4096;   t = id - 2048; }
    else                 { W = W3; dst = g_bfrag + 20480;  t = id - 10240; }
    int lane = t & 31, nt = (t >> 5) & 15, kc = t >> 9;
    int k = kc * 8 + (lane & 3);
    int n = nt * 8 + (lane >> 2);
    uint32_t b0 = f2tf(W[k * EMBD + n]);
    uint32_t b1 = f2tf(W[(k + 4) * EMBD + n]);
    int p = ((kc * 16 + nt) * 32 + lane) * 2;
    dst[p] = b0; dst[p + 1] = b1;
}

// ---------------- one dense layer, warp-level tf32 mma ----------------
// Warp computes its 16 act rows x 128 outputs. MODE 0: relu + tf32-cvt store;
// MODE 1: plain fp32 store (layer 3).
template<int KC, int MODE>
__device__ __forceinline__ void do_layer(const uint32_t* __restrict__ bf,
                                         const float* __restrict__ bias,
                                         uint32_t* __restrict__ actw,
                                         int g, int q, int lane) {
    float c[16][4];
    #pragma unroll
    for (int nt = 0; nt < 16; nt++) {
        float bl = bias[nt * 8 + 2 * q], bh = bias[nt * 8 + 2 * q + 1];
        c[nt][0] = bl; c[nt][1] = bh; c[nt][2] = bl; c[nt][3] = bh;
    }
    #pragma unroll 4
    for (int kc = 0; kc < KC; kc++) {
        uint32_t a0 = actw[g * ACTS + kc * 8 + q];
        uint32_t a1 = actw[(g + 8) * ACTS + kc * 8 + q];
        uint32_t a2 = actw[g * ACTS + kc * 8 + q + 4];
        uint32_t a3 = actw[(g + 8) * ACTS + kc * 8 + q + 4];
        const uint2* bp = (const uint2*)bf + (kc * 16) * 32 + lane;
        #pragma unroll
        for (int nt = 0; nt < 16; nt++) {
            uint2 b = bp[nt * 32];
            mma_tf32(c[nt], a0, a1, a2, a3, b.x, b.y);
        }
    }
    #pragma unroll
    for (int nt = 0; nt < 16; nt++) {
        uint32_t* lo = actw + g * ACTS + nt * 8 + 2 * q;
        uint32_t* hi = actw + (g + 8) * ACTS + nt * 8 + 2 * q;
        if (MODE == 0) {
            *(uint2*)lo = make_uint2(f2tf(fmaxf(c[nt][0], 0.f)), f2tf(fmaxf(c[nt][1], 0.f)));
            *(uint2*)hi = make_uint2(f2tf(fmaxf(c[nt][2], 0.f)), f2tf(fmaxf(c[nt][3], 0.f)));
        } else {
            *(float2*)lo = make_float2(c[nt][0], c[nt][1]);
            *(float2*)hi = make_float2(c[nt][2], c[nt][3]);
        }
    }
}

// ---------------- persistent tensor-core local MLP ----------------
// 148 CTAs x 256 threads (8 warps). Warp w owns voters [w*16, w*16+16) of each
// 128-voter tile. No inter-warp sync between layers (warps touch only own rows).
__global__ __launch_bounds__(256, 1)
void local_kernel(const float* __restrict__ x, const int* __restrict__ idx_raw,
                  const float* __restrict__ b1, const float* __restrict__ b2,
                  const float* __restrict__ b3) {
    uint32_t* BF1 = smu + OFF_BF1;
    uint32_t* BF2 = smu + OFF_BF2;
    uint32_t* BF3 = smu + OFF_BF3;
    uint32_t* ACT = smu + OFF_ACT;
    float* bs1 = (float*)(smu + OFF_B1);
    float* bs2 = (float*)(smu + OFF_B2);
    float* bs3 = (float*)(smu + OFF_B3);
    __shared__ int segs[128];

    int tid = threadIdx.x, wid = tid >> 5, lane = tid & 31;
    int g = lane >> 2, q = lane & 3;

    // stage weight fragments + biases once
    {
        const uint4* src = (const uint4*)g_bfrag;
        uint4* dst = (uint4*)smu;
        for (int i = tid; i < 36864 / 4; i += 256) dst[i] = src[i];
        if (tid < 128) { bs1[tid] = b1[tid]; bs2[tid] = b2[tid]; bs3[tid] = b3[tid]; }
    }
    __syncthreads();

    uint32_t* actw = ACT + wid * 16 * ACTS;
    const int is32 = g_idx_is32;

    for (int tile = blockIdx.x; tile < NTILE; tile += gridDim.x) {
        if (tid < 128) {
            int gi = tile * 128 + tid;
            segs[tid] = is32 ? idx_raw[gi] : idx_raw[2 * gi];   // int64 LE low word
        }
        // stage x rows (warp's 16 rows; coalesced float4; tf32-cvt)
        {
            const float4* xp = (const float4*)(x + ((size_t)tile * 128 + wid * 16) * CAND);
            #pragma unroll
            for (int i = 0; i < 4; i++) {
                int f = lane + 32 * i;           // 128 float4 covering 16 rows
                float4 t = xp[f];
                uint32_t* d = actw + (f >> 3) * ACTS + (f & 7) * 4;
                d[0] = f2tf(t.x); d[1] = f2tf(t.y); d[2] = f2tf(t.z); d[3] = f2tf(t.w);
            }
        }
        do_layer<4, 0>(BF1, bs1, actw, g, q, lane);
        do_layer<16, 0>(BF2, bs2, actw, g, q, lane);
        do_layer<16, 1>(BF3, bs3, actw, g, q, lane);
        __syncthreads();

        // sorted segment reduction: thread (col j, voter-half) over run-lengths
        {
            int j = tid & 127, half = tid >> 7;
            const float* actf = (const float*)ACT;
            int vv = half * 64, vend = vv + 64;
            while (vv < vend) {
                int s = segs[vv];
                float sum = 0.0f;
                do { sum += actf[vv * ACTS + j]; vv++; } while (vv < vend && segs[vv] == s);
                atomicAdd(&g_agg[(size_t)s * EMBD + j], sum);
            }
        }
        __syncthreads();
    }
}

// ---------------- global MLP (unchanged fp32 path, passing) ----------------
__device__ __forceinline__ unsigned long long pk2(float v) {
    unsigned long long r;
    asm("mov.b64 %0, {%1, %1};" : "=l"(r) : "f"(v));
    return r;
}
__device__ __forceinline__ void fma2(unsigned long long& d,
                                     unsigned long long a, unsigned long long b) {
    asm("fma.rn.f32x2 %0, %1, %2, %0;" : "+l"(d) : "l"(a), "l"(b));
}
__device__ __forceinline__ float2 upk(unsigned long long v) {
    float2 f;
    asm("mov.b64 {%0, %1}, %2;" : "=f"(f.x), "=f"(f.y) : "l"(v));
    return f;
}

template<int K, bool RELU>
__device__ __forceinline__ void layer_chunk2(const float* __restrict__ hrow,
                                             const float* __restrict__ W,
                                             const float* __restrict__ bvec,
                                             float* __restrict__ outp,
                                             int j0, int ldw) {
    unsigned long long acc[16];
    const ulonglong2* bp = (const ulonglong2*)(bvec + j0);
    #pragma unroll
    for (int q = 0; q < 8; q++) { ulonglong2 t = bp[q]; acc[2*q] = t.x; acc[2*q+1] = t.y; }
    #pragma unroll 4
    for (int k = 0; k < K; k++) {
        unsigned long long h2 = pk2(hrow[k]);
        const ulonglong2* wp = (const ulonglong2*)(W + (size_t)k * ldw + j0);
        #pragma unroll
        for (int q = 0; q < 8; q++) {
            ulonglong2 w = wp[q];
            fma2(acc[2*q],     w.x, h2);
            fma2(acc[2*q + 1], w.y, h2);
        }
    }
    #pragma unroll
    for (int q = 0; q < 16; q++) {
        float2 f = upk(acc[q]);
        outp[2*q]     = RELU ? fmaxf(f.x, 0.0f) : f.x;
        outp[2*q + 1] = RELU ? fmaxf(f.y, 0.0f) : f.y;
    }
}

__global__ __launch_bounds__(128, 4)
void global_kernel(const float* __restrict__ W1, const float* __restrict__ b1,
                   const float* __restrict__ W2, const float* __restrict__ b2,
                   const float* __restrict__ W3, const float* __restrict__ b3,
                   float* __restrict__ out) {
    float* A = (float*)smu;
    float* B = (float*)smu + SPB * RS;
    int tid = threadIdx.x;
    int s   = tid >> 2;
    int c   = tid & 3;
    int s0  = blockIdx.x * SPB;

    for (int i = tid; i < SPB * EMBD; i += 128) {
        int r2 = i >> 7, k = i & 127;
        A[r2 * RS + k] = g_agg[(size_t)(s0 + r2) * EMBD + k];
    }
    __syncthreads();

    layer_chunk2<EMBD, true>(&A[s * RS], W1, b1, &B[s * RS + 32 * c], 32 * c, EMBD);
    __syncthreads();

    layer_chunk2<EMBD, true>(&B[s * RS], W2, b2, &A[s * RS + 32 * c], 32 * c, EMBD);
    __syncthreads();

    if (c == 0) {
        float sc[32];
        layer_chunk2<EMBD, false>(&A[s * RS], W3, b3, sc, 0, CAND);

        float m = sc[0];
        #pragma unroll
        for (int j = 1; j < 32; j++) m = fmaxf(m, sc[j]);
        float sum = 0.0f;
        #pragma unroll
        for (int j = 0; j < 32; j++) sum += expf(sc[j] - m);
        float lse = m + logf(sum);

        float* op = out + (size_t)(s0 + s) * CAND;
        #pragma unroll
        for (int j = 0; j < 32; j++) op[j] = sc[j] - lse;
    }
}

extern "C" void kernel_launch(void* const* d_in, const int* in_sizes, int n_in,
                              void* d_out, int out_size) {
    const float* x       = (const float*)d_in[0];
    const int*   idx_raw = (const int*)d_in[1];   // int32 OR int64 — detected at runtime
    const float* lW1 = (const float*)d_in[2];  const float* lb1 = (const float*)d_in[3];
    const float* lW2 = (const float*)d_in[4];  const float* lb2 = (const float*)d_in[5];
    const float* lW3 = (const float*)d_in[6];  const float* lb3 = (const float*)d_in[7];
    const float* gW1 = (const float*)d_in[8];  const float* gb1 = (const float*)d_in[9];
    const float* gW2 = (const float*)d_in[10]; const float* gb2 = (const float*)d_in[11];
    const float* gW3 = (const float*)d_in[12]; const float* gb3 = (const float*)d_in[13];
    float* out = (float*)d_out;

    const int SMEM_GLOBAL = 2 * SPB * RS * sizeof(float);   // 33024
    cudaFuncSetAttribute(local_kernel,  cudaFuncAttributeMaxDynamicSharedMemorySize, SMEM_LOCAL);
    cudaFuncSetAttribute(global_kernel, cudaFuncAttributeMaxDynamicSharedMemorySize, SMEM_GLOBAL);

    wprep_kernel<<<72, 256>>>(lW1, lW2, lW3);
    zero_agg_kernel<<<NSEG * EMBD / 512, 512>>>();
    detect_index_kernel<<<(NVOT / 2) / 512, 512>>>(idx_raw);
    local_kernel<<<148, 256, SMEM_LOCAL>>>(x, idx_raw, lb1, lb2, lb3);
    global_kernel<<<NSEG / SPB, 128, SMEM_GLOBAL>>>(gW1, gb1, gW2, gb2, gW3, gb3, out);
}